// round 5
// baseline (speedup 1.0000x reference)
#include <cuda_runtime.h>
#include <cuda_bf16.h>

// ---------------------------------------------------------------------------
// Upsampling via two bf16 mma.sync GEMMs (HMMA path; tcgen05 rejected by the
// harness's .target sm_103 lowering).
//   stage 1: y_down = lrelu(x_down @ W_lin + b_lin)       [65536 x 256 x 128]
//   stage 2: out = lrelu([x_up | gather(y_down)] @ W_fus + b_fus)
//                                                         [262144 x 256 x 128]
// fp32 emulation: x = hi + lo (bf16); D = Ahi*Bhi + Ahi*Blo + Alo*Bhi.
// R5: CTA tile 128m x 64n (N split via blockIdx.y), 256 thr, 2 CTAs/SM for
// latency hiding; tensor-pipe floor ~85us on stage 2.
// ---------------------------------------------------------------------------

constexpr int BATCH = 4, N_DOWN = 16384, N_UP = 65536;
constexpr float NSLOPE = 0.1f;

__device__ float g_ydown[(size_t)BATCH * N_DOWN * 128];
__device__ int g_idx_is64;

// Pre-split, pre-transposed W^T images: per stage [hi | lo], each [128 n][264 k] bf16
constexpr int BSTR = 264;                     // bf16/row: 256 + 8 pad -> 528 B
constexpr int BHSIZE = 128 * BSTR * 2;        // 67584 B (full-N hi image)
__device__ __align__(16) unsigned char g_Bt[2][2 * BHSIZE];

constexpr int ASTR = 72;                      // bf16/row: 64 + 8 pad -> 144 B
constexpr int AHSIZE = 128 * ASTR * 2;        // 18432 B

// per-CTA smem: B half-N images (64 rows) + A chunk hi/lo
constexpr int BHALF = 64 * BSTR * 2;          // 33792 B
constexpr int SM_ROWPTR = 0;                  // 128 x 8B gather pointers
constexpr int SM_B = 1024;                    // [BH 33792 | BL 33792]
constexpr int SM_A = SM_B + 2 * BHALF;        // [AH 18432 | AL 18432]
constexpr int SM_TOTAL = SM_A + 2 * AHSIZE;   // 105472 B  (2 CTAs/SM)

__device__ __forceinline__ float lrelu(float x) { return x > 0.0f ? x : NSLOPE * x; }

__device__ __forceinline__ unsigned smem_u32(const void* p) {
    unsigned a;
    asm("{ .reg .u64 t; cvta.to.shared.u64 t, %1; cvt.u32.u64 %0, t; }" : "=r"(a) : "l"(p));
    return a;
}

#define LDSM4(r, a) asm volatile( \
    "ldmatrix.sync.aligned.m8n8.x4.shared.b16 {%0,%1,%2,%3}, [%4];" \
    : "=r"((r)[0]), "=r"((r)[1]), "=r"((r)[2]), "=r"((r)[3]) : "r"(a))
#define LDSM2(r, a) asm volatile( \
    "ldmatrix.sync.aligned.m8n8.x2.shared.b16 {%0,%1}, [%2];" \
    : "=r"((r)[0]), "=r"((r)[1]) : "r"(a))
#define MMA(d, a, b) asm volatile( \
    "mma.sync.aligned.m16n8k16.row.col.f32.bf16.bf16.f32 " \
    "{%0,%1,%2,%3}, {%4,%5,%6,%7}, {%8,%9}, {%0,%1,%2,%3};" \
    : "+f"((d)[0]), "+f"((d)[1]), "+f"((d)[2]), "+f"((d)[3]) \
    : "r"((a)[0]), "r"((a)[1]), "r"((a)[2]), "r"((a)[3]), "r"((b)[0]), "r"((b)[1]))

__device__ __forceinline__ void split2(float a, float b, unsigned& h, unsigned& l) {
    __nv_bfloat16 ha = __float2bfloat16(a), hb = __float2bfloat16(b);
    float ra = a - __bfloat162float(ha), rb = b - __bfloat162float(hb);
    __nv_bfloat16 la = __float2bfloat16(ra), lb = __float2bfloat16(rb);
    h = (unsigned)__bfloat16_as_ushort(ha) | ((unsigned)__bfloat16_as_ushort(hb) << 16);
    l = (unsigned)__bfloat16_as_ushort(la) | ((unsigned)__bfloat16_as_ushort(lb) << 16);
}

// ---- probe index dtype: int64 has odd 32-bit words == 0 for values < 16384 ----
__global__ void detect_idx_kernel(const int* __restrict__ idx32) {
    int all0 = 1;
#pragma unroll
    for (int i = 1; i < 32; i += 2) all0 &= (idx32[i] == 0);
    g_idx_is64 = all0;
}

// ---- pre-split + transpose W[k][n] -> BT[n][k] (padded), hi and lo images ----
__global__ void prep_w(const float* __restrict__ Wl, const float* __restrict__ Wf) {
    int idx = blockIdx.x * 256 + threadIdx.x;   // 0..65535
    int stage = idx >> 15;
    int rem = idx & 32767;
    int k = rem >> 7, n = rem & 127;
    const float* W = stage ? Wf : Wl;
    float w = W[k * 128 + n];
    __nv_bfloat16 h = __float2bfloat16(w);
    float r = w - __bfloat162float(h);
    __nv_bfloat16 l = __float2bfloat16(r);
    unsigned char* base = g_Bt[stage];
    int off = n * (BSTR * 2) + k * 2;
    *(unsigned short*)(base + off) = __bfloat16_as_ushort(h);
    *(unsigned short*)(base + BHSIZE + off) = __bfloat16_as_ushort(l);
}

template <int STAGE>
__global__ __launch_bounds__(256, 2)
void gemm_mma(const float* __restrict__ A0,      // s1: x_down[M,256]; s2: x_up[M,128]
              const int* __restrict__ idx_raw,   // s2 only
              const unsigned char* __restrict__ Bimg,
              const float* __restrict__ bias,
              float* __restrict__ outp) {
    extern __shared__ __align__(16) char s[];
    const unsigned sbase = smem_u32(s);
    const int tid = threadIdx.x;
    const int lane = tid & 31;
    const int w = tid >> 5;
    const int wm = w >> 1, wn = w & 1;           // 4x2 warp grid, 32m x 32n each
    const int m_blk = blockIdx.x * 128;
    const int n0 = blockIdx.y * 64;              // this CTA's N half

    // gather pointers (stage 2)
    if (STAGE == 2 && tid < 128) {
        const int mg = m_blk + tid;
        const int b = mg >> 16;
        int g;
        if (g_idx_is64) g = idx_raw[2 * mg]; else g = idx_raw[mg];
        ((const float**)(s + SM_ROWPTR))[tid] = g_ydown + (size_t)(b * N_DOWN + g) * 128;
    }
    // copy this CTA's 64-n slice of B (hi and lo; rows are contiguous)
    {
        const float4* sh = (const float4*)(Bimg + (size_t)n0 * (BSTR * 2));
        const float4* sl = (const float4*)(Bimg + BHSIZE + (size_t)n0 * (BSTR * 2));
        float4* dh = (float4*)(s + SM_B);
        float4* dl = (float4*)(s + SM_B + BHALF);
        for (int i = tid; i < BHALF / 16; i += 256) { dh[i] = sh[i]; dl[i] = sl[i]; }
    }
    __syncthreads();

    // conversion role: row cr (0..127), 32-float half h
    const int cr = tid >> 1;
    const int h = tid & 1;
    const int mg = m_blk + cr;
    const float* rowp = (STAGE == 2) ? ((const float**)(s + SM_ROWPTR))[cr] : nullptr;

    // per-lane ldmatrix base addresses
    const unsigned pA = sbase + SM_A + (wm * 32 + (lane & 15)) * 144 + (lane >> 4) * 16;
    const unsigned pB = sbase + SM_B + (wn * 32 + (lane & 7)) * 528 + ((lane >> 3) & 1) * 16;

    float d[2][4][4];
#pragma unroll
    for (int mf = 0; mf < 2; ++mf)
#pragma unroll
        for (int nf = 0; nf < 4; ++nf)
#pragma unroll
            for (int i = 0; i < 4; ++i) d[mf][nf][i] = 0.0f;

    for (int c = 0; c < 4; ++c) {
        // ---- convert A chunk [128 x 64] fp32 -> bf16 hi/lo into padded smem ----
        const float* src;
        if (STAGE == 1)       src = A0 + (size_t)mg * 256 + c * 64 + h * 32;
        else if (c < 2)       src = A0 + (size_t)mg * 128 + c * 64 + h * 32;
        else                  src = rowp + (c - 2) * 64 + h * 32;
        {
            char* ah = s + SM_A + cr * 144 + h * 64;
            char* al = ah + AHSIZE;
#pragma unroll
            for (int g = 0; g < 2; ++g) {
                const float4 u0 = ((const float4*)src)[4 * g + 0];
                const float4 u1 = ((const float4*)src)[4 * g + 1];
                const float4 u2 = ((const float4*)src)[4 * g + 2];
                const float4 u3 = ((const float4*)src)[4 * g + 3];
                unsigned h0, h1, h2, h3, h4, h5, h6, h7;
                unsigned l0, l1, l2, l3, l4, l5, l6, l7;
                split2(u0.x, u0.y, h0, l0); split2(u0.z, u0.w, h1, l1);
                split2(u1.x, u1.y, h2, l2); split2(u1.z, u1.w, h3, l3);
                split2(u2.x, u2.y, h4, l4); split2(u2.z, u2.w, h5, l5);
                split2(u3.x, u3.y, h6, l6); split2(u3.z, u3.w, h7, l7);
                ((uint4*)ah)[2 * g + 0] = make_uint4(h0, h1, h2, h3);
                ((uint4*)ah)[2 * g + 1] = make_uint4(h4, h5, h6, h7);
                ((uint4*)al)[2 * g + 0] = make_uint4(l0, l1, l2, l3);
                ((uint4*)al)[2 * g + 1] = make_uint4(l4, l5, l6, l7);
            }
        }
        __syncthreads();

        // ---- MMA over this 64-k chunk: 4 ksteps of 16 ----
#pragma unroll
        for (int ks = 0; ks < 4; ++ks) {
            unsigned aH[2][4], aL[2][4];
#pragma unroll
            for (int mf = 0; mf < 2; ++mf) {
                const unsigned pa = pA + mf * (16 * 144) + ks * 32;
                LDSM4(aH[mf], pa);
                LDSM4(aL[mf], pa + AHSIZE);
            }
            const unsigned kb = (c * 64 + ks * 16) * 2;
#pragma unroll
            for (int nf = 0; nf < 4; ++nf) {
                unsigned bH[2], bL[2];
                const unsigned pb = pB + nf * (8 * 528) + kb;
                LDSM2(bH, pb);
                LDSM2(bL, pb + BHALF);
#pragma unroll
                for (int mf = 0; mf < 2; ++mf) {
                    MMA(d[mf][nf], aH[mf], bH);
                    MMA(d[mf][nf], aH[mf], bL);
                    MMA(d[mf][nf], aL[mf], bH);
                }
            }
        }
        __syncthreads();   // before next chunk overwrites A smem
    }

    // ---- epilogue: bias + leaky relu, float2 stores ----
    float* dst = (STAGE == 1) ? g_ydown : outp;
    const int colL = wn * 32 + 2 * (lane & 3);   // local col within 64-n half
    const int row0 = m_blk + wm * 32 + (lane >> 2);

    float2 bb[4];
#pragma unroll
    for (int nf = 0; nf < 4; ++nf) bb[nf] = *(const float2*)(bias + n0 + colL + nf * 8);

#pragma unroll
    for (int mf = 0; mf < 2; ++mf) {
        float* r0 = dst + (size_t)(row0 + mf * 16) * 128 + n0;
        float* r1 = r0 + 8 * 128;
#pragma unroll
        for (int nf = 0; nf < 4; ++nf) {
            const int cc = colL + nf * 8;
            *(float2*)(r0 + cc) = make_float2(lrelu(d[mf][nf][0] + bb[nf].x),
                                              lrelu(d[mf][nf][1] + bb[nf].y));
            *(float2*)(r1 + cc) = make_float2(lrelu(d[mf][nf][2] + bb[nf].x),
                                              lrelu(d[mf][nf][3] + bb[nf].y));
        }
    }
}

extern "C" void kernel_launch(void* const* d_in, const int* in_sizes, int n_in,
                              void* d_out, int out_size) {
    const float* x_down = (const float*)d_in[0];
    const float* x_up   = (const float*)d_in[1];
    const int*   up_idx = (const int*)d_in[2];
    const float* W_lin  = (const float*)d_in[3];
    const float* b_lin  = (const float*)d_in[4];
    const float* W_fus  = (const float*)d_in[5];
    const float* b_fus  = (const float*)d_in[6];
    float* out = (float*)d_out;

    cudaFuncSetAttribute(gemm_mma<1>, cudaFuncAttributeMaxDynamicSharedMemorySize, SM_TOTAL);
    cudaFuncSetAttribute(gemm_mma<2>, cudaFuncAttributeMaxDynamicSharedMemorySize, SM_TOTAL);

    detect_idx_kernel<<<1, 1>>>(up_idx);
    prep_w<<<256, 256>>>(W_lin, W_fus);

    unsigned char* bimg0;
    cudaGetSymbolAddress((void**)&bimg0, g_Bt);
    unsigned char* bimg1 = bimg0 + 2 * BHSIZE;

    dim3 g1((BATCH * N_DOWN) / 128, 2);
    dim3 g2((BATCH * N_UP) / 128, 2);
    gemm_mma<1><<<g1, 256, SM_TOTAL>>>(x_down, nullptr, bimg0, b_lin, nullptr);
    gemm_mma<2><<<g2, 256, SM_TOTAL>>>(x_up, up_idx, bimg1, b_fus, out);
}

// round 9
// speedup vs baseline: 1.3653x; 1.3653x over previous
#include <cuda_runtime.h>
#include <cuda_bf16.h>

// ---------------------------------------------------------------------------
// Upsampling via two bf16 mma.sync GEMMs (HMMA path; tcgen05 rejected by the
// harness's .target sm_103 lowering).
//   stage 1: y_down = lrelu(x_down @ W_lin + b_lin)       [65536 x 256 x 128]
//   stage 2: out = lrelu([x_up | gather(y_down)] @ W_fus + b_fus)
//                                                         [262144 x 256 x 128]
// fp32 emulation: x = hi + lo (bf16); D = Ahi*Bhi + Ahi*Blo + Alo*Bhi.
// R6/R7: 128x128 / 512-thr tile (R4); A smem double-buffered -> one barrier
// per k-chunk; A global loads prefetched into registers behind MMA.
// (R6 bench was an infra failure; identical source resubmitted.)
// ---------------------------------------------------------------------------

constexpr int BATCH = 4, N_DOWN = 16384, N_UP = 65536;
constexpr float NSLOPE = 0.1f;

__device__ float g_ydown[(size_t)BATCH * N_DOWN * 128];
__device__ int g_idx_is64;

// Pre-split, pre-transposed W^T images: per stage [hi | lo], each [128 n][264 k] bf16
constexpr int BSTR = 264;                    // bf16/row: 256 + 8 pad -> 528 B
constexpr int BHSIZE = 128 * BSTR * 2;       // 67584 B
__device__ __align__(16) unsigned char g_Bt[2][2 * BHSIZE];

constexpr int ASTR = 72;                     // bf16/row: 64 + 8 pad -> 144 B
constexpr int AHSIZE = 128 * ASTR * 2;       // 18432 B
constexpr int ABUF = 2 * AHSIZE;             // one buffer = [AH | AL] = 36864 B

// smem layout (dynamic)
constexpr int SM_ROWPTR = 0;                 // 128 x 8B gather pointers (stage 2)
constexpr int SM_B = 1024;                   // 2*BHSIZE = 135168 (hi | lo)
constexpr int SM_A = SM_B + 2 * BHSIZE;      // 2 buffers x 36864
constexpr int SM_TOTAL = SM_A + 2 * ABUF;    // 209920 B

__device__ __forceinline__ float lrelu(float x) { return x > 0.0f ? x : NSLOPE * x; }

__device__ __forceinline__ unsigned smem_u32(const void* p) {
    unsigned a;
    asm("{ .reg .u64 t; cvta.to.shared.u64 t, %1; cvt.u32.u64 %0, t; }" : "=r"(a) : "l"(p));
    return a;
}

#define LDSM4(r, a) asm volatile( \
    "ldmatrix.sync.aligned.m8n8.x4.shared.b16 {%0,%1,%2,%3}, [%4];" \
    : "=r"((r)[0]), "=r"((r)[1]), "=r"((r)[2]), "=r"((r)[3]) : "r"(a))
#define LDSM2(r, a) asm volatile( \
    "ldmatrix.sync.aligned.m8n8.x2.shared.b16 {%0,%1}, [%2];" \
    : "=r"((r)[0]), "=r"((r)[1]) : "r"(a))
#define MMA(d, a, b) asm volatile( \
    "mma.sync.aligned.m16n8k16.row.col.f32.bf16.bf16.f32 " \
    "{%0,%1,%2,%3}, {%4,%5,%6,%7}, {%8,%9}, {%0,%1,%2,%3};" \
    : "+f"((d)[0]), "+f"((d)[1]), "+f"((d)[2]), "+f"((d)[3]) \
    : "r"((a)[0]), "r"((a)[1]), "r"((a)[2]), "r"((a)[3]), "r"((b)[0]), "r"((b)[1]))

__device__ __forceinline__ void split2(float a, float b, unsigned& h, unsigned& l) {
    __nv_bfloat16 ha = __float2bfloat16(a), hb = __float2bfloat16(b);
    float ra = a - __bfloat162float(ha), rb = b - __bfloat162float(hb);
    __nv_bfloat16 la = __float2bfloat16(ra), lb = __float2bfloat16(rb);
    h = (unsigned)__bfloat16_as_ushort(ha) | ((unsigned)__bfloat16_as_ushort(hb) << 16);
    l = (unsigned)__bfloat16_as_ushort(la) | ((unsigned)__bfloat16_as_ushort(lb) << 16);
}

// ---- probe index dtype: int64 has odd 32-bit words == 0 for values < 16384 ----
__global__ void detect_idx_kernel(const int* __restrict__ idx32) {
    int all0 = 1;
#pragma unroll
    for (int i = 1; i < 32; i += 2) all0 &= (idx32[i] == 0);
    g_idx_is64 = all0;
}

// ---- pre-split + transpose W[k][n] -> BT[n][k] (padded), hi and lo images ----
__global__ void prep_w(const float* __restrict__ Wl, const float* __restrict__ Wf) {
    int idx = blockIdx.x * 256 + threadIdx.x;   // 0..65535
    int stage = idx >> 15;
    int rem = idx & 32767;
    int k = rem >> 7, n = rem & 127;
    const float* W = stage ? Wf : Wl;
    float w = W[k * 128 + n];
    __nv_bfloat16 h = __float2bfloat16(w);
    float r = w - __bfloat162float(h);
    __nv_bfloat16 l = __float2bfloat16(r);
    unsigned char* base = g_Bt[stage];
    int off = n * (BSTR * 2) + k * 2;
    *(unsigned short*)(base + off) = __bfloat16_as_ushort(h);
    *(unsigned short*)(base + BHSIZE + off) = __bfloat16_as_ushort(l);
}

template <int STAGE>
__global__ __launch_bounds__(512, 1)
void gemm_mma(const float* __restrict__ A0,      // s1: x_down[M,256]; s2: x_up[M,128]
              const int* __restrict__ idx_raw,   // s2 only
              const unsigned char* __restrict__ Bimg,
              const float* __restrict__ bias,
              float* __restrict__ outp) {
    extern __shared__ __align__(16) char s[];
    const unsigned sbase = smem_u32(s);
    const int tid = threadIdx.x;
    const int lane = tid & 31;
    const int w = tid >> 5;
    const int wm = w >> 2, wn = w & 3;           // 4x4 warp grid, 32m x 32n each
    const int m_blk = blockIdx.x * 128;

    // gather pointers (stage 2)
    if (STAGE == 2 && tid < 128) {
        const int mg = m_blk + tid;
        const int b = mg >> 16;
        int g;
        if (g_idx_is64) g = idx_raw[2 * mg]; else g = idx_raw[mg];
        ((const float**)(s + SM_ROWPTR))[tid] = g_ydown + (size_t)(b * N_DOWN + g) * 128;
    }
    // copy full B image (hi|lo, padded) into smem
    {
        const float4* src = (const float4*)Bimg;
        float4* dst = (float4*)(s + SM_B);
        for (int i = tid; i < (2 * BHSIZE) / 16; i += 512) dst[i] = src[i];
    }
    __syncthreads();

    // conversion role: row cr (0..127), 16-float segment seg
    const int cr = tid >> 2;
    const int seg = (tid & 3) * 16;
    const int mg = m_blk + cr;
    const float* rowp = (STAGE == 2) ? ((const float**)(s + SM_ROWPTR))[cr] : nullptr;

    // per-lane ldmatrix base addresses
    const unsigned pA0 = sbase + SM_A + (wm * 32 + (lane & 15)) * 144 + (lane >> 4) * 16;
    const unsigned pB = sbase + SM_B + (wn * 32 + (lane & 7)) * 528 + ((lane >> 3) & 1) * 16;

    float d[2][4][4];
#pragma unroll
    for (int mf = 0; mf < 2; ++mf)
#pragma unroll
        for (int nf = 0; nf < 4; ++nf)
#pragma unroll
            for (int i = 0; i < 4; ++i) d[mf][nf][i] = 0.0f;

    // chunk source pointer
    auto srcp = [&](int c) -> const float* {
        if (STAGE == 1) return A0 + (size_t)mg * 256 + c * 64 + seg;
        if (c < 2)      return A0 + (size_t)mg * 128 + c * 64 + seg;
        return rowp + (c - 2) * 64 + seg;
    };

    // prefetch chunk 0 into registers
    float4 u0, u1, u2, u3;
    {
        const float* p = srcp(0);
        u0 = ((const float4*)p)[0]; u1 = ((const float4*)p)[1];
        u2 = ((const float4*)p)[2]; u3 = ((const float4*)p)[3];
    }

    for (int c = 0; c < 4; ++c) {
        const int bo = (c & 1) * ABUF;

        // ---- convert prefetched A chunk -> bf16 hi/lo into buffer (c&1) ----
        {
            char* ah = s + SM_A + bo + cr * 144 + seg * 2;
            char* al = ah + AHSIZE;
            unsigned h0, h1, h2, h3, h4, h5, h6, h7, l0, l1, l2, l3, l4, l5, l6, l7;
            split2(u0.x, u0.y, h0, l0); split2(u0.z, u0.w, h1, l1);
            split2(u1.x, u1.y, h2, l2); split2(u1.z, u1.w, h3, l3);
            split2(u2.x, u2.y, h4, l4); split2(u2.z, u2.w, h5, l5);
            split2(u3.x, u3.y, h6, l6); split2(u3.z, u3.w, h7, l7);
            ((uint4*)ah)[0] = make_uint4(h0, h1, h2, h3);
            ((uint4*)ah)[1] = make_uint4(h4, h5, h6, h7);
            ((uint4*)al)[0] = make_uint4(l0, l1, l2, l3);
            ((uint4*)al)[1] = make_uint4(l4, l5, l6, l7);
        }
        __syncthreads();   // buffer (c&1) ready; also guarantees MMA(c-1) done

        // ---- prefetch next chunk's globals (rides behind the MMA stream) ----
        if (c < 3) {
            const float* p = srcp(c + 1);
            u0 = ((const float4*)p)[0]; u1 = ((const float4*)p)[1];
            u2 = ((const float4*)p)[2]; u3 = ((const float4*)p)[3];
        }

        // ---- MMA over this 64-k chunk: 4 ksteps of 16 ----
        const unsigned pA = pA0 + bo;
#pragma unroll
        for (int ks = 0; ks < 4; ++ks) {
            unsigned aH[2][4], aL[2][4];
#pragma unroll
            for (int mf = 0; mf < 2; ++mf) {
                const unsigned pa = pA + mf * (16 * 144) + ks * 32;
                LDSM4(aH[mf], pa);
                LDSM4(aL[mf], pa + AHSIZE);
            }
            const unsigned kb = (c * 64 + ks * 16) * 2;
#pragma unroll
            for (int nf = 0; nf < 4; ++nf) {
                unsigned bH[2], bL[2];
                const unsigned pb = pB + nf * (8 * 528) + kb;
                LDSM2(bH, pb);
                LDSM2(bL, pb + BHSIZE);
#pragma unroll
                for (int mf = 0; mf < 2; ++mf) {
                    MMA(d[mf][nf], aH[mf], bH);
                    MMA(d[mf][nf], aH[mf], bL);
                    MMA(d[mf][nf], aL[mf], bH);
                }
            }
        }
        // no trailing barrier: next iteration's post-convert barrier protects reuse
    }

    // ---- epilogue: bias + leaky relu, float2 stores ----
    float* dst = (STAGE == 1) ? g_ydown : outp;
    const int col0 = wn * 32 + 2 * (lane & 3);
    const int row0 = m_blk + wm * 32 + (lane >> 2);

    float2 bb[4];
#pragma unroll
    for (int nf = 0; nf < 4; ++nf) bb[nf] = *(const float2*)(bias + col0 + nf * 8);

#pragma unroll
    for (int mf = 0; mf < 2; ++mf) {
        float* r0 = dst + (size_t)(row0 + mf * 16) * 128;
        float* r1 = r0 + 8 * 128;
#pragma unroll
        for (int nf = 0; nf < 4; ++nf) {
            const int cc = col0 + nf * 8;
            *(float2*)(r0 + cc) = make_float2(lrelu(d[mf][nf][0] + bb[nf].x),
                                              lrelu(d[mf][nf][1] + bb[nf].y));
            *(float2*)(r1 + cc) = make_float2(lrelu(d[mf][nf][2] + bb[nf].x),
                                              lrelu(d[mf][nf][3] + bb[nf].y));
        }
    }
}

extern "C" void kernel_launch(void* const* d_in, const int* in_sizes, int n_in,
                              void* d_out, int out_size) {
    const float* x_down = (const float*)d_in[0];
    const float* x_up   = (const float*)d_in[1];
    const int*   up_idx = (const int*)d_in[2];
    const float* W_lin  = (const float*)d_in[3];
    const float* b_lin  = (const float*)d_in[4];
    const float* W_fus  = (const float*)d_in[5];
    const float* b_fus  = (const float*)d_in[6];
    float* out = (float*)d_out;

    cudaFuncSetAttribute(gemm_mma<1>, cudaFuncAttributeMaxDynamicSharedMemorySize, SM_TOTAL);
    cudaFuncSetAttribute(gemm_mma<2>, cudaFuncAttributeMaxDynamicSharedMemorySize, SM_TOTAL);

    detect_idx_kernel<<<1, 1>>>(up_idx);
    prep_w<<<256, 256>>>(W_lin, W_fus);

    unsigned char* bimg0;
    cudaGetSymbolAddress((void**)&bimg0, g_Bt);
    unsigned char* bimg1 = bimg0 + 2 * BHSIZE;

    gemm_mma<1><<<(BATCH * N_DOWN) / 128, 512, SM_TOTAL>>>(x_down, nullptr, bimg0, b_lin, nullptr);
    gemm_mma<2><<<(BATCH * N_UP) / 128, 512, SM_TOTAL>>>(x_up, up_idx, bimg1, b_fus, out);
}

// round 12
// speedup vs baseline: 1.4470x; 1.0598x over previous
#include <cuda_runtime.h>
#include <cuda_bf16.h>

// ---------------------------------------------------------------------------
// Upsampling via two bf16 mma.sync GEMMs (HMMA path; tcgen05 rejected by the
// harness's .target sm_103 lowering).
//   stage 1: y_down = lrelu(x_down @ W_lin + b_lin)       [65536 x 256 x 128]
//   stage 2: out = lrelu([x_up | gather(y_down)] @ W_fus + b_fus)
//                                                         [262144 x 256 x 128]
// fp32 emulation: x = hi + lo (bf16); D = Ahi*Bhi + Ahi*Blo + Alo*Bhi.
// R11: R10 with the B x4-ldmatrix fragment mapping FIXED:
//   LDSM4 #1 @ +0      -> nf0 (regs 0-1), nf2 (regs 2-3)
//   LDSM4 #2 @ +8*528  -> nf1 (regs 4-5), nf3 (regs 6-7)
//   consume via offset map {0,4,2,6}.
// Term-major MMA ordering (accumulator reuse distance 8) kept from R10.
// ---------------------------------------------------------------------------

constexpr int BATCH = 4, N_DOWN = 16384, N_UP = 65536;
constexpr float NSLOPE = 0.1f;

__device__ float g_ydown[(size_t)BATCH * N_DOWN * 128];
__device__ int g_idx_is64;

// Pre-split, pre-transposed W^T images: per stage [hi | lo], each [128 n][264 k] bf16
constexpr int BSTR = 264;                    // bf16/row: 256 + 8 pad -> 528 B
constexpr int BHSIZE = 128 * BSTR * 2;       // 67584 B
__device__ __align__(16) unsigned char g_Bt[2][2 * BHSIZE];

constexpr int ASTR = 72;                     // bf16/row: 64 + 8 pad -> 144 B
constexpr int AHSIZE = 128 * ASTR * 2;       // 18432 B
constexpr int ABUF = 2 * AHSIZE;             // one buffer = [AH | AL] = 36864 B

// smem layout (dynamic)
constexpr int SM_ROWPTR = 0;                 // 128 x 8B gather pointers (stage 2)
constexpr int SM_B = 1024;                   // 2*BHSIZE = 135168 (hi | lo)
constexpr int SM_A = SM_B + 2 * BHSIZE;      // 2 buffers x 36864
constexpr int SM_TOTAL = SM_A + 2 * ABUF;    // 209920 B

__device__ __forceinline__ float lrelu(float x) { return x > 0.0f ? x : NSLOPE * x; }

__device__ __forceinline__ unsigned smem_u32(const void* p) {
    unsigned a;
    asm("{ .reg .u64 t; cvta.to.shared.u64 t, %1; cvt.u32.u64 %0, t; }" : "=r"(a) : "l"(p));
    return a;
}

#define LDSM4(r, a) asm volatile( \
    "ldmatrix.sync.aligned.m8n8.x4.shared.b16 {%0,%1,%2,%3}, [%4];" \
    : "=r"((r)[0]), "=r"((r)[1]), "=r"((r)[2]), "=r"((r)[3]) : "r"(a))
#define MMA(d, a, b) asm volatile( \
    "mma.sync.aligned.m16n8k16.row.col.f32.bf16.bf16.f32 " \
    "{%0,%1,%2,%3}, {%4,%5,%6,%7}, {%8,%9}, {%0,%1,%2,%3};" \
    : "+f"((d)[0]), "+f"((d)[1]), "+f"((d)[2]), "+f"((d)[3]) \
    : "r"((a)[0]), "r"((a)[1]), "r"((a)[2]), "r"((a)[3]), "r"((b)[0]), "r"((b)[1]))

__device__ __forceinline__ void split2(float a, float b, unsigned& h, unsigned& l) {
    __nv_bfloat16 ha = __float2bfloat16(a), hb = __float2bfloat16(b);
    float ra = a - __bfloat162float(ha), rb = b - __bfloat162float(hb);
    __nv_bfloat16 la = __float2bfloat16(ra), lb = __float2bfloat16(rb);
    h = (unsigned)__bfloat16_as_ushort(ha) | ((unsigned)__bfloat16_as_ushort(hb) << 16);
    l = (unsigned)__bfloat16_as_ushort(la) | ((unsigned)__bfloat16_as_ushort(lb) << 16);
}

// ---- probe index dtype: int64 has odd 32-bit words == 0 for values < 16384 ----
__global__ void detect_idx_kernel(const int* __restrict__ idx32) {
    int all0 = 1;
#pragma unroll
    for (int i = 1; i < 32; i += 2) all0 &= (idx32[i] == 0);
    g_idx_is64 = all0;
}

// ---- pre-split + transpose W[k][n] -> BT[n][k] (padded), hi and lo images ----
__global__ void prep_w(const float* __restrict__ Wl, const float* __restrict__ Wf) {
    int idx = blockIdx.x * 256 + threadIdx.x;   // 0..65535
    int stage = idx >> 15;
    int rem = idx & 32767;
    int k = rem >> 7, n = rem & 127;
    const float* W = stage ? Wf : Wl;
    float w = W[k * 128 + n];
    __nv_bfloat16 h = __float2bfloat16(w);
    float r = w - __bfloat162float(h);
    __nv_bfloat16 l = __float2bfloat16(r);
    unsigned char* base = g_Bt[stage];
    int off = n * (BSTR * 2) + k * 2;
    *(unsigned short*)(base + off) = __bfloat16_as_ushort(h);
    *(unsigned short*)(base + BHSIZE + off) = __bfloat16_as_ushort(l);
}

template <int STAGE>
__global__ __launch_bounds__(512, 1)
void gemm_mma(const float* __restrict__ A0,      // s1: x_down[M,256]; s2: x_up[M,128]
              const int* __restrict__ idx_raw,   // s2 only
              const unsigned char* __restrict__ Bimg,
              const float* __restrict__ bias,
              float* __restrict__ outp) {
    extern __shared__ __align__(16) char s[];
    const unsigned sbase = smem_u32(s);
    const int tid = threadIdx.x;
    const int lane = tid & 31;
    const int w = tid >> 5;
    const int wm = w >> 2, wn = w & 3;           // 4x4 warp grid, 32m x 32n each
    const int m_blk = blockIdx.x * 128;

    // gather pointers (stage 2)
    if (STAGE == 2 && tid < 128) {
        const int mg = m_blk + tid;
        const int b = mg >> 16;
        int g;
        if (g_idx_is64) g = idx_raw[2 * mg]; else g = idx_raw[mg];
        ((const float**)(s + SM_ROWPTR))[tid] = g_ydown + (size_t)(b * N_DOWN + g) * 128;
    }
    // copy full B image (hi|lo, padded) into smem
    {
        const float4* src = (const float4*)Bimg;
        float4* dst = (float4*)(s + SM_B);
        for (int i = tid; i < (2 * BHSIZE) / 16; i += 512) dst[i] = src[i];
    }
    __syncthreads();

    // conversion role: row cr (0..127), 16-float segment seg
    const int cr = tid >> 2;
    const int seg = (tid & 3) * 16;
    const int mg = m_blk + cr;
    const float* rowp = (STAGE == 2) ? ((const float**)(s + SM_ROWPTR))[cr] : nullptr;

    // per-lane ldmatrix base addresses
    const unsigned pA0 = sbase + SM_A + (wm * 32 + (lane & 15)) * 144 + (lane >> 4) * 16;
    // B x4: lane groups 0-7/8-15 -> rows r..r+7 klo/khi; groups 16-23/24-31 ->
    // rows r+16..r+23 klo/khi. So one LDSM4 covers nf and nf+2.
    const unsigned pBq = sbase + SM_B
                       + (wn * 32 + (lane >> 4) * 16 + (lane & 7)) * 528
                       + ((lane >> 3) & 1) * 16;

    float d[2][4][4];
#pragma unroll
    for (int mf = 0; mf < 2; ++mf)
#pragma unroll
        for (int nf = 0; nf < 4; ++nf)
#pragma unroll
            for (int i = 0; i < 4; ++i) d[mf][nf][i] = 0.0f;

    // chunk source pointer
    auto srcp = [&](int c) -> const float* {
        if (STAGE == 1) return A0 + (size_t)mg * 256 + c * 64 + seg;
        if (c < 2)      return A0 + (size_t)mg * 128 + c * 64 + seg;
        return rowp + (c - 2) * 64 + seg;
    };

    // prefetch chunk 0 into registers
    float4 u0, u1, u2, u3;
    {
        const float* p = srcp(0);
        u0 = ((const float4*)p)[0]; u1 = ((const float4*)p)[1];
        u2 = ((const float4*)p)[2]; u3 = ((const float4*)p)[3];
    }

    for (int c = 0; c < 4; ++c) {
        const int bo = (c & 1) * ABUF;

        // ---- convert prefetched A chunk -> bf16 hi/lo into buffer (c&1) ----
        {
            char* ah = s + SM_A + bo + cr * 144 + seg * 2;
            char* al = ah + AHSIZE;
            unsigned h0, h1, h2, h3, h4, h5, h6, h7, l0, l1, l2, l3, l4, l5, l6, l7;
            split2(u0.x, u0.y, h0, l0); split2(u0.z, u0.w, h1, l1);
            split2(u1.x, u1.y, h2, l2); split2(u1.z, u1.w, h3, l3);
            split2(u2.x, u2.y, h4, l4); split2(u2.z, u2.w, h5, l5);
            split2(u3.x, u3.y, h6, l6); split2(u3.z, u3.w, h7, l7);
            ((uint4*)ah)[0] = make_uint4(h0, h1, h2, h3);
            ((uint4*)ah)[1] = make_uint4(h4, h5, h6, h7);
            ((uint4*)al)[0] = make_uint4(l0, l1, l2, l3);
            ((uint4*)al)[1] = make_uint4(l4, l5, l6, l7);
        }
        __syncthreads();   // buffer (c&1) ready; also guarantees MMA(c-1) done

        // ---- prefetch next chunk's globals (rides behind the MMA stream) ----
        if (c < 3) {
            const float* p = srcp(c + 1);
            u0 = ((const float4*)p)[0]; u1 = ((const float4*)p)[1];
            u2 = ((const float4*)p)[2]; u3 = ((const float4*)p)[3];
        }

        // ---- MMA over this 64-k chunk: 4 ksteps of 16 ----
        const unsigned pA = pA0 + bo;
#pragma unroll
        for (int ks = 0; ks < 4; ++ks) {
            // load ALL fragments first (8 ldmatrix, latencies overlap)
            unsigned aH[2][4], aL[2][4];
            unsigned bH[8], bL[8];
#pragma unroll
            for (int mf = 0; mf < 2; ++mf) {
                const unsigned pa = pA + mf * (16 * 144) + ks * 32;
                LDSM4(aH[mf], pa);
                LDSM4(aL[mf], pa + AHSIZE);
            }
            {
                const unsigned kb = (c * 64 + ks * 16) * 2;
                LDSM4(bH + 0, pBq + kb);                 // regs 0-1: nf0, regs 2-3: nf2
                LDSM4(bH + 4, pBq + 8 * 528 + kb);       // regs 4-5: nf1, regs 6-7: nf3
                LDSM4(bL + 0, pBq + BHSIZE + kb);
                LDSM4(bL + 4, pBq + BHSIZE + 8 * 528 + kb);
            }
            // fragment offset map: nf -> reg pair start
            const int boff[4] = {0, 4, 2, 6};
            // term-major passes: same-accumulator reuse distance = 8 MMAs
#pragma unroll
            for (int nf = 0; nf < 4; ++nf)
#pragma unroll
                for (int mf = 0; mf < 2; ++mf)
                    MMA(d[mf][nf], aH[mf], bH + boff[nf]);
#pragma unroll
            for (int nf = 0; nf < 4; ++nf)
#pragma unroll
                for (int mf = 0; mf < 2; ++mf)
                    MMA(d[mf][nf], aH[mf], bL + boff[nf]);
#pragma unroll
            for (int nf = 0; nf < 4; ++nf)
#pragma unroll
                for (int mf = 0; mf < 2; ++mf)
                    MMA(d[mf][nf], aL[mf], bH + boff[nf]);
        }
        // no trailing barrier: next iteration's post-convert barrier protects reuse
    }

    // ---- epilogue: bias + leaky relu, float2 stores ----
    float* dst = (STAGE == 1) ? g_ydown : outp;
    const int col0 = wn * 32 + 2 * (lane & 3);
    const int row0 = m_blk + wm * 32 + (lane >> 2);

    float2 bb[4];
#pragma unroll
    for (int nf = 0; nf < 4; ++nf) bb[nf] = *(const float2*)(bias + col0 + nf * 8);

#pragma unroll
    for (int mf = 0; mf < 2; ++mf) {
        float* r0 = dst + (size_t)(row0 + mf * 16) * 128;
        float* r1 = r0 + 8 * 128;
#pragma unroll
        for (int nf = 0; nf < 4; ++nf) {
            const int cc = col0 + nf * 8;
            *(float2*)(r0 + cc) = make_float2(lrelu(d[mf][nf][0] + bb[nf].x),
                                              lrelu(d[mf][nf][1] + bb[nf].y));
            *(float2*)(r1 + cc) = make_float2(lrelu(d[mf][nf][2] + bb[nf].x),
                                              lrelu(d[mf][nf][3] + bb[nf].y));
        }
    }
}

extern "C" void kernel_launch(void* const* d_in, const int* in_sizes, int n_in,
                              void* d_out, int out_size) {
    const float* x_down = (const float*)d_in[0];
    const float* x_up   = (const float*)d_in[1];
    const int*   up_idx = (const int*)d_in[2];
    const float* W_lin  = (const float*)d_in[3];
    const float* b_lin  = (const float*)d_in[4];
    const float* W_fus  = (const float*)d_in[5];
    const float* b_fus  = (const float*)d_in[6];
    float* out = (float*)d_out;

    cudaFuncSetAttribute(gemm_mma<1>, cudaFuncAttributeMaxDynamicSharedMemorySize, SM_TOTAL);
    cudaFuncSetAttribute(gemm_mma<2>, cudaFuncAttributeMaxDynamicSharedMemorySize, SM_TOTAL);

    detect_idx_kernel<<<1, 1>>>(up_idx);
    prep_w<<<256, 256>>>(W_lin, W_fus);

    unsigned char* bimg0;
    cudaGetSymbolAddress((void**)&bimg0, g_Bt);
    unsigned char* bimg1 = bimg0 + 2 * BHSIZE;

    gemm_mma<1><<<(BATCH * N_DOWN) / 128, 512, SM_TOTAL>>>(x_down, nullptr, bimg0, b_lin, nullptr);
    gemm_mma<2><<<(BATCH * N_UP) / 128, 512, SM_TOTAL>>>(x_up, up_idx, bimg1, b_fus, out);
}

// round 13
// speedup vs baseline: 1.6760x; 1.1582x over previous
#include <cuda_runtime.h>
#include <cuda_bf16.h>

// ---------------------------------------------------------------------------
// Upsampling via two bf16 mma.sync GEMMs (HMMA path; tcgen05 rejected by the
// harness's .target sm_103 lowering).
//   stage 1: y_down = lrelu(x_down @ W_lin + b_lin)       [65536 x 256 x 128]
//   stage 2: out = lrelu([x_up | gather(y_down)] @ W_fus + b_fus)
//                                                         [262144 x 256 x 128]
// fp32 emulation: x = hi + lo (bf16); D = Ahi*Bhi + Ahi*Blo + Alo*Bhi.
// R13: 1024 threads / 32 warps, warp tile 16m x 32n (8x4 grid). Low register
// footprint (~60/thr) removes the 128-reg WAR serialization seen in R12;
// 8 warps/SMSP interleave LDSM latency. Term-major MMA + fixed B x4 mapping.
// ---------------------------------------------------------------------------

constexpr int BATCH = 4, N_DOWN = 16384, N_UP = 65536;
constexpr float NSLOPE = 0.1f;

__device__ float g_ydown[(size_t)BATCH * N_DOWN * 128];
__device__ int g_idx_is64;

// Pre-split, pre-transposed W^T images: per stage [hi | lo], each [128 n][264 k] bf16
constexpr int BSTR = 264;                    // bf16/row: 256 + 8 pad -> 528 B
constexpr int BHSIZE = 128 * BSTR * 2;       // 67584 B
__device__ __align__(16) unsigned char g_Bt[2][2 * BHSIZE];

constexpr int ASTR = 72;                     // bf16/row: 64 + 8 pad -> 144 B
constexpr int AHSIZE = 128 * ASTR * 2;       // 18432 B
constexpr int ABUF = 2 * AHSIZE;             // one buffer = [AH | AL] = 36864 B

// smem layout (dynamic)
constexpr int SM_ROWPTR = 0;                 // 128 x 8B gather pointers (stage 2)
constexpr int SM_B = 1024;                   // 2*BHSIZE = 135168 (hi | lo)
constexpr int SM_A = SM_B + 2 * BHSIZE;      // 2 buffers x 36864
constexpr int SM_TOTAL = SM_A + 2 * ABUF;    // 209920 B

__device__ __forceinline__ float lrelu(float x) { return x > 0.0f ? x : NSLOPE * x; }

__device__ __forceinline__ unsigned smem_u32(const void* p) {
    unsigned a;
    asm("{ .reg .u64 t; cvta.to.shared.u64 t, %1; cvt.u32.u64 %0, t; }" : "=r"(a) : "l"(p));
    return a;
}

#define LDSM4(r, a) asm volatile( \
    "ldmatrix.sync.aligned.m8n8.x4.shared.b16 {%0,%1,%2,%3}, [%4];" \
    : "=r"((r)[0]), "=r"((r)[1]), "=r"((r)[2]), "=r"((r)[3]) : "r"(a))
#define MMA(d, a, b) asm volatile( \
    "mma.sync.aligned.m16n8k16.row.col.f32.bf16.bf16.f32 " \
    "{%0,%1,%2,%3}, {%4,%5,%6,%7}, {%8,%9}, {%0,%1,%2,%3};" \
    : "+f"((d)[0]), "+f"((d)[1]), "+f"((d)[2]), "+f"((d)[3]) \
    : "r"((a)[0]), "r"((a)[1]), "r"((a)[2]), "r"((a)[3]), "r"((b)[0]), "r"((b)[1]))

__device__ __forceinline__ void split2(float a, float b, unsigned& h, unsigned& l) {
    __nv_bfloat16 ha = __float2bfloat16(a), hb = __float2bfloat16(b);
    float ra = a - __bfloat162float(ha), rb = b - __bfloat162float(hb);
    __nv_bfloat16 la = __float2bfloat16(ra), lb = __float2bfloat16(rb);
    h = (unsigned)__bfloat16_as_ushort(ha) | ((unsigned)__bfloat16_as_ushort(hb) << 16);
    l = (unsigned)__bfloat16_as_ushort(la) | ((unsigned)__bfloat16_as_ushort(lb) << 16);
}

// ---- probe index dtype: int64 has odd 32-bit words == 0 for values < 16384 ----
__global__ void detect_idx_kernel(const int* __restrict__ idx32) {
    int all0 = 1;
#pragma unroll
    for (int i = 1; i < 32; i += 2) all0 &= (idx32[i] == 0);
    g_idx_is64 = all0;
}

// ---- pre-split + transpose W[k][n] -> BT[n][k] (padded), hi and lo images ----
__global__ void prep_w(const float* __restrict__ Wl, const float* __restrict__ Wf) {
    int idx = blockIdx.x * 256 + threadIdx.x;   // 0..65535
    int stage = idx >> 15;
    int rem = idx & 32767;
    int k = rem >> 7, n = rem & 127;
    const float* W = stage ? Wf : Wl;
    float w = W[k * 128 + n];
    __nv_bfloat16 h = __float2bfloat16(w);
    float r = w - __bfloat162float(h);
    __nv_bfloat16 l = __float2bfloat16(r);
    unsigned char* base = g_Bt[stage];
    int off = n * (BSTR * 2) + k * 2;
    *(unsigned short*)(base + off) = __bfloat16_as_ushort(h);
    *(unsigned short*)(base + BHSIZE + off) = __bfloat16_as_ushort(l);
}

template <int STAGE>
__global__ __launch_bounds__(1024, 1)
void gemm_mma(const float* __restrict__ A0,      // s1: x_down[M,256]; s2: x_up[M,128]
              const int* __restrict__ idx_raw,   // s2 only
              const unsigned char* __restrict__ Bimg,
              const float* __restrict__ bias,
              float* __restrict__ outp) {
    extern __shared__ __align__(16) char s[];
    const unsigned sbase = smem_u32(s);
    const int tid = threadIdx.x;
    const int lane = tid & 31;
    const int w = tid >> 5;
    const int wm = w >> 2, wn = w & 3;           // 8x4 warp grid, 16m x 32n each
    const int m_blk = blockIdx.x * 128;

    // gather pointers (stage 2)
    if (STAGE == 2 && tid < 128) {
        const int mg = m_blk + tid;
        const int b = mg >> 16;
        int g;
        if (g_idx_is64) g = idx_raw[2 * mg]; else g = idx_raw[mg];
        ((const float**)(s + SM_ROWPTR))[tid] = g_ydown + (size_t)(b * N_DOWN + g) * 128;
    }
    // copy full B image (hi|lo, padded) into smem
    {
        const float4* src = (const float4*)Bimg;
        float4* dst = (float4*)(s + SM_B);
        for (int i = tid; i < (2 * BHSIZE) / 16; i += 1024) dst[i] = src[i];
    }
    __syncthreads();

    // conversion role: row cr (0..127), 8-float segment seg
    const int cr = tid >> 3;
    const int seg = (tid & 7) * 8;
    const int mg = m_blk + cr;
    const float* rowp = (STAGE == 2) ? ((const float**)(s + SM_ROWPTR))[cr] : nullptr;

    // per-lane ldmatrix base addresses
    // A x4 over one 16-row tile: rows wm*16 + (lane&15), 16B half (lane>>4)
    const unsigned pA0 = sbase + SM_A + (wm * 16 + (lane & 15)) * 144 + (lane >> 4) * 16;
    // B x4: lane groups 0-7/8-15 -> rows r..r+7 klo/khi; 16-23/24-31 -> rows
    // r+16..r+23 -> one LDSM4 covers nf and nf+2 (offset map {0,4,2,6}).
    const unsigned pBq = sbase + SM_B
                       + (wn * 32 + (lane >> 4) * 16 + (lane & 7)) * 528
                       + ((lane >> 3) & 1) * 16;

    float d[4][4];
#pragma unroll
    for (int nf = 0; nf < 4; ++nf)
#pragma unroll
        for (int i = 0; i < 4; ++i) d[nf][i] = 0.0f;

    // chunk source pointer
    auto srcp = [&](int c) -> const float* {
        if (STAGE == 1) return A0 + (size_t)mg * 256 + c * 64 + seg;
        if (c < 2)      return A0 + (size_t)mg * 128 + c * 64 + seg;
        return rowp + (c - 2) * 64 + seg;
    };

    // prefetch chunk 0 into registers
    float4 u0, u1;
    {
        const float* p = srcp(0);
        u0 = ((const float4*)p)[0]; u1 = ((const float4*)p)[1];
    }

    for (int c = 0; c < 4; ++c) {
        const int bo = (c & 1) * ABUF;

        // ---- convert prefetched A chunk -> bf16 hi/lo into buffer (c&1) ----
        {
            char* ah = s + SM_A + bo + cr * 144 + seg * 2;
            char* al = ah + AHSIZE;
            unsigned h0, h1, h2, h3, l0, l1, l2, l3;
            split2(u0.x, u0.y, h0, l0); split2(u0.z, u0.w, h1, l1);
            split2(u1.x, u1.y, h2, l2); split2(u1.z, u1.w, h3, l3);
            *(uint4*)ah = make_uint4(h0, h1, h2, h3);
            *(uint4*)al = make_uint4(l0, l1, l2, l3);
        }
        __syncthreads();   // buffer (c&1) ready; also guarantees MMA(c-1) done

        // ---- prefetch next chunk's globals (rides behind the MMA stream) ----
        if (c < 3) {
            const float* p = srcp(c + 1);
            u0 = ((const float4*)p)[0]; u1 = ((const float4*)p)[1];
        }

        // ---- MMA over this 64-k chunk: 4 ksteps of 16 ----
        const unsigned pA = pA0 + bo;
#pragma unroll
        for (int ks = 0; ks < 4; ++ks) {
            // load ALL fragments first (6 ldmatrix, latencies overlap)
            unsigned aH[4], aL[4];
            unsigned bH[8], bL[8];
            {
                const unsigned pa = pA + ks * 32;
                LDSM4(aH, pa);
                LDSM4(aL, pa + AHSIZE);
            }
            {
                const unsigned kb = (c * 64 + ks * 16) * 2;
                LDSM4(bH + 0, pBq + kb);                 // regs 0-1: nf0, 2-3: nf2
                LDSM4(bH + 4, pBq + 8 * 528 + kb);       // regs 4-5: nf1, 6-7: nf3
                LDSM4(bL + 0, pBq + BHSIZE + kb);
                LDSM4(bL + 4, pBq + BHSIZE + 8 * 528 + kb);
            }
            const int boff[4] = {0, 4, 2, 6};
            // term-major passes (per-accumulator order HH, HL, LH preserved)
#pragma unroll
            for (int nf = 0; nf < 4; ++nf) MMA(d[nf], aH, bH + boff[nf]);
#pragma unroll
            for (int nf = 0; nf < 4; ++nf) MMA(d[nf], aH, bL + boff[nf]);
#pragma unroll
            for (int nf = 0; nf < 4; ++nf) MMA(d[nf], aL, bH + boff[nf]);
        }
        // no trailing barrier: next iteration's post-convert barrier protects reuse
    }

    // ---- epilogue: bias + leaky relu, float2 stores ----
    float* dst = (STAGE == 1) ? g_ydown : outp;
    const int col0 = wn * 32 + 2 * (lane & 3);
    const int row0 = m_blk + wm * 16 + (lane >> 2);

    float2 bb[4];
#pragma unroll
    for (int nf = 0; nf < 4; ++nf) bb[nf] = *(const float2*)(bias + col0 + nf * 8);

    float* r0 = dst + (size_t)row0 * 128;
    float* r1 = r0 + 8 * 128;
#pragma unroll
    for (int nf = 0; nf < 4; ++nf) {
        const int cc = col0 + nf * 8;
        *(float2*)(r0 + cc) = make_float2(lrelu(d[nf][0] + bb[nf].x),
                                          lrelu(d[nf][1] + bb[nf].y));
        *(float2*)(r1 + cc) = make_float2(lrelu(d[nf][2] + bb[nf].x),
                                          lrelu(d[nf][3] + bb[nf].y));
    }
}

extern "C" void kernel_launch(void* const* d_in, const int* in_sizes, int n_in,
                              void* d_out, int out_size) {
    const float* x_down = (const float*)d_in[0];
    const float* x_up   = (const float*)d_in[1];
    const int*   up_idx = (const int*)d_in[2];
    const float* W_lin  = (const float*)d_in[3];
    const float* b_lin  = (const float*)d_in[4];
    const float* W_fus  = (const float*)d_in[5];
    const float* b_fus  = (const float*)d_in[6];
    float* out = (float*)d_out;

    cudaFuncSetAttribute(gemm_mma<1>, cudaFuncAttributeMaxDynamicSharedMemorySize, SM_TOTAL);
    cudaFuncSetAttribute(gemm_mma<2>, cudaFuncAttributeMaxDynamicSharedMemorySize, SM_TOTAL);

    detect_idx_kernel<<<1, 1>>>(up_idx);
    prep_w<<<256, 256>>>(W_lin, W_fus);

    unsigned char* bimg0;
    cudaGetSymbolAddress((void**)&bimg0, g_Bt);
    unsigned char* bimg1 = bimg0 + 2 * BHSIZE;

    gemm_mma<1><<<(BATCH * N_DOWN) / 128, 1024, SM_TOTAL>>>(x_down, nullptr, bimg0, b_lin, nullptr);
    gemm_mma<2><<<(BATCH * N_UP) / 128, 1024, SM_TOTAL>>>(x_up, up_idx, bimg1, b_fus, out);
}

// round 15
// speedup vs baseline: 2.3080x; 1.3771x over previous
#include <cuda_runtime.h>
#include <cuda_fp16.h>

// ---------------------------------------------------------------------------
// Upsampling via two fp16 mma.sync GEMMs (HMMA path; tcgen05 rejected by the
// harness's .target sm_103 lowering).
//   stage 1: y_down = lrelu(x_down @ W_lin + b_lin)       [65536 x 256 x 128]
//   stage 2: out = lrelu([x_up | gather(y_down)] @ W_fus + b_fus)
//                                                         [262144 x 256 x 128]
// R14 numerics: A = aH + aL (fp16 pair, ~22-bit exact); B single fp16
// (representation error ~2^-11 random -> norm rel_err ~3e-4 < 1e-3).
// D = aH*B + aL*B in fp32 accumulators: 8 MMA + 4 LDSM4 per kstep per warp
// (was 12 + 6 with 3-term bf16) -> tensor AND smem floors both cut 1/3.
// 1024 thr / 32 warps, warp tile 16m x 32n, A double-buffered, term-major.
// ---------------------------------------------------------------------------

constexpr int BATCH = 4, N_DOWN = 16384, N_UP = 65536;
constexpr float NSLOPE = 0.1f;

__device__ float g_ydown[(size_t)BATCH * N_DOWN * 128];
__device__ int g_idx_is64;

// Pre-converted, pre-transposed W^T fp16 image per stage: [128 n][264 k]
constexpr int BSTR = 264;                    // fp16/row: 256 + 8 pad -> 528 B
constexpr int BHSIZE = 128 * BSTR * 2;       // 67584 B
__device__ __align__(16) unsigned char g_Bt[2][BHSIZE];

constexpr int ASTR = 72;                     // fp16/row: 64 + 8 pad -> 144 B
constexpr int AHSIZE = 128 * ASTR * 2;       // 18432 B
constexpr int ABUF = 2 * AHSIZE;             // one buffer = [AH | AL] = 36864 B

// smem layout (dynamic)
constexpr int SM_ROWPTR = 0;                 // 128 x 8B gather pointers (stage 2)
constexpr int SM_B = 1024;                   // BHSIZE = 67584 (single fp16 image)
constexpr int SM_A = SM_B + BHSIZE;          // 2 buffers x 36864
constexpr int SM_TOTAL = SM_A + 2 * ABUF;    // 142336 B

__device__ __forceinline__ float lrelu(float x) { return x > 0.0f ? x : NSLOPE * x; }

__device__ __forceinline__ unsigned smem_u32(const void* p) {
    unsigned a;
    asm("{ .reg .u64 t; cvta.to.shared.u64 t, %1; cvt.u32.u64 %0, t; }" : "=r"(a) : "l"(p));
    return a;
}

#define LDSM4(r, a) asm volatile( \
    "ldmatrix.sync.aligned.m8n8.x4.shared.b16 {%0,%1,%2,%3}, [%4];" \
    : "=r"((r)[0]), "=r"((r)[1]), "=r"((r)[2]), "=r"((r)[3]) : "r"(a))
#define MMA(d, a, b) asm volatile( \
    "mma.sync.aligned.m16n8k16.row.col.f32.f16.f16.f32 " \
    "{%0,%1,%2,%3}, {%4,%5,%6,%7}, {%8,%9}, {%0,%1,%2,%3};" \
    : "+f"((d)[0]), "+f"((d)[1]), "+f"((d)[2]), "+f"((d)[3]) \
    : "r"((a)[0]), "r"((a)[1]), "r"((a)[2]), "r"((a)[3]), "r"((b)[0]), "r"((b)[1]))

// fp32 -> fp16 hi + fp16 lo (packed pairs)
__device__ __forceinline__ void split2(float a, float b, unsigned& h, unsigned& l) {
    __half ha = __float2half_rn(a), hb = __float2half_rn(b);
    float ra = a - __half2float(ha), rb = b - __half2float(hb);
    __half la = __float2half_rn(ra), lb = __float2half_rn(rb);
    h = (unsigned)__half_as_ushort(ha) | ((unsigned)__half_as_ushort(hb) << 16);
    l = (unsigned)__half_as_ushort(la) | ((unsigned)__half_as_ushort(lb) << 16);
}

// ---- probe index dtype: int64 has odd 32-bit words == 0 for values < 16384 ----
__global__ void detect_idx_kernel(const int* __restrict__ idx32) {
    int all0 = 1;
#pragma unroll
    for (int i = 1; i < 32; i += 2) all0 &= (idx32[i] == 0);
    g_idx_is64 = all0;
}

// ---- convert + transpose W[k][n] -> BT[n][k] (padded) fp16 image ----
__global__ void prep_w(const float* __restrict__ Wl, const float* __restrict__ Wf) {
    int idx = blockIdx.x * 256 + threadIdx.x;   // 0..65535
    int stage = idx >> 15;
    int rem = idx & 32767;
    int k = rem >> 7, n = rem & 127;
    const float* W = stage ? Wf : Wl;
    float w = W[k * 128 + n];
    int off = n * (BSTR * 2) + k * 2;
    *(unsigned short*)(g_Bt[stage] + off) = __half_as_ushort(__float2half_rn(w));
}

template <int STAGE>
__global__ __launch_bounds__(1024, 1)
void gemm_mma(const float* __restrict__ A0,      // s1: x_down[M,256]; s2: x_up[M,128]
              const int* __restrict__ idx_raw,   // s2 only
              const unsigned char* __restrict__ Bimg,
              const float* __restrict__ bias,
              float* __restrict__ outp) {
    extern __shared__ __align__(16) char s[];
    const unsigned sbase = smem_u32(s);
    const int tid = threadIdx.x;
    const int lane = tid & 31;
    const int w = tid >> 5;
    const int wm = w >> 2, wn = w & 3;           // 8x4 warp grid, 16m x 32n each
    const int m_blk = blockIdx.x * 128;

    // gather pointers (stage 2)
    if (STAGE == 2 && tid < 128) {
        const int mg = m_blk + tid;
        const int b = mg >> 16;
        int g;
        if (g_idx_is64) g = idx_raw[2 * mg]; else g = idx_raw[mg];
        ((const float**)(s + SM_ROWPTR))[tid] = g_ydown + (size_t)(b * N_DOWN + g) * 128;
    }
    // copy fp16 B image into smem
    {
        const float4* src = (const float4*)Bimg;
        float4* dst = (float4*)(s + SM_B);
        for (int i = tid; i < BHSIZE / 16; i += 1024) dst[i] = src[i];
    }
    __syncthreads();

    // conversion role: row cr (0..127), 8-float segment seg
    const int cr = tid >> 3;
    const int seg = (tid & 7) * 8;
    const int mg = m_blk + cr;
    const float* rowp = (STAGE == 2) ? ((const float**)(s + SM_ROWPTR))[cr] : nullptr;

    // per-lane ldmatrix base addresses
    const unsigned pA0 = sbase + SM_A + (wm * 16 + (lane & 15)) * 144 + (lane >> 4) * 16;
    // B x4: groups 0-7/8-15 -> rows r..r+7 klo/khi; 16-23/24-31 -> rows r+16..r+23
    // -> one LDSM4 covers nf and nf+2 (offset map {0,4,2,6}).
    const unsigned pBq = sbase + SM_B
                       + (wn * 32 + (lane >> 4) * 16 + (lane & 7)) * 528
                       + ((lane >> 3) & 1) * 16;

    float d[4][4];
#pragma unroll
    for (int nf = 0; nf < 4; ++nf)
#pragma unroll
        for (int i = 0; i < 4; ++i) d[nf][i] = 0.0f;

    // chunk source pointer
    auto srcp = [&](int c) -> const float* {
        if (STAGE == 1) return A0 + (size_t)mg * 256 + c * 64 + seg;
        if (c < 2)      return A0 + (size_t)mg * 128 + c * 64 + seg;
        return rowp + (c - 2) * 64 + seg;
    };

    // prefetch chunk 0 into registers
    float4 u0, u1;
    {
        const float* p = srcp(0);
        u0 = ((const float4*)p)[0]; u1 = ((const float4*)p)[1];
    }

    for (int c = 0; c < 4; ++c) {
        const int bo = (c & 1) * ABUF;

        // ---- convert prefetched A chunk -> fp16 hi/lo into buffer (c&1) ----
        {
            char* ah = s + SM_A + bo + cr * 144 + seg * 2;
            char* al = ah + AHSIZE;
            unsigned h0, h1, h2, h3, l0, l1, l2, l3;
            split2(u0.x, u0.y, h0, l0); split2(u0.z, u0.w, h1, l1);
            split2(u1.x, u1.y, h2, l2); split2(u1.z, u1.w, h3, l3);
            *(uint4*)ah = make_uint4(h0, h1, h2, h3);
            *(uint4*)al = make_uint4(l0, l1, l2, l3);
        }
        __syncthreads();   // buffer (c&1) ready; also guarantees MMA(c-1) done

        // ---- prefetch next chunk's globals (rides behind the MMA stream) ----
        if (c < 3) {
            const float* p = srcp(c + 1);
            u0 = ((const float4*)p)[0]; u1 = ((const float4*)p)[1];
        }

        // ---- MMA over this 64-k chunk: 4 ksteps of 16 ----
        const unsigned pA = pA0 + bo;
#pragma unroll
        for (int ks = 0; ks < 4; ++ks) {
            // load ALL fragments first (4 ldmatrix, latencies overlap)
            unsigned aH[4], aL[4];
            unsigned bF[8];
            {
                const unsigned pa = pA + ks * 32;
                LDSM4(aH, pa);
                LDSM4(aL, pa + AHSIZE);
            }
            {
                const unsigned kb = (c * 64 + ks * 16) * 2;
                LDSM4(bF + 0, pBq + kb);                 // regs 0-1: nf0, 2-3: nf2
                LDSM4(bF + 4, pBq + 8 * 528 + kb);       // regs 4-5: nf1, 6-7: nf3
            }
            const int boff[4] = {0, 4, 2, 6};
            // term-major passes (per-accumulator order: hi then lo)
#pragma unroll
            for (int nf = 0; nf < 4; ++nf) MMA(d[nf], aH, bF + boff[nf]);
#pragma unroll
            for (int nf = 0; nf < 4; ++nf) MMA(d[nf], aL, bF + boff[nf]);
        }
        // no trailing barrier: next iteration's post-convert barrier protects reuse
    }

    // ---- epilogue: bias + leaky relu, float2 stores ----
    float* dst = (STAGE == 1) ? g_ydown : outp;
    const int col0 = wn * 32 + 2 * (lane & 3);
    const int row0 = m_blk + wm * 16 + (lane >> 2);

    float2 bb[4];
#pragma unroll
    for (int nf = 0; nf < 4; ++nf) bb[nf] = *(const float2*)(bias + col0 + nf * 8);

    float* r0 = dst + (size_t)row0 * 128;
    float* r1 = r0 + 8 * 128;
#pragma unroll
    for (int nf = 0; nf < 4; ++nf) {
        const int cc = col0 + nf * 8;
        *(float2*)(r0 + cc) = make_float2(lrelu(d[nf][0] + bb[nf].x),
                                          lrelu(d[nf][1] + bb[nf].y));
        *(float2*)(r1 + cc) = make_float2(lrelu(d[nf][2] + bb[nf].x),
                                          lrelu(d[nf][3] + bb[nf].y));
    }
}

extern "C" void kernel_launch(void* const* d_in, const int* in_sizes, int n_in,
                              void* d_out, int out_size) {
    const float* x_down = (const float*)d_in[0];
    const float* x_up   = (const float*)d_in[1];
    const int*   up_idx = (const int*)d_in[2];
    const float* W_lin  = (const float*)d_in[3];
    const float* b_lin  = (const float*)d_in[4];
    const float* W_fus  = (const float*)d_in[5];
    const float* b_fus  = (const float*)d_in[6];
    float* out = (float*)d_out;

    cudaFuncSetAttribute(gemm_mma<1>, cudaFuncAttributeMaxDynamicSharedMemorySize, SM_TOTAL);
    cudaFuncSetAttribute(gemm_mma<2>, cudaFuncAttributeMaxDynamicSharedMemorySize, SM_TOTAL);

    detect_idx_kernel<<<1, 1>>>(up_idx);
    prep_w<<<256, 256>>>(W_lin, W_fus);

    unsigned char* bimg0;
    cudaGetSymbolAddress((void**)&bimg0, g_Bt);
    unsigned char* bimg1 = bimg0 + BHSIZE;

    gemm_mma<1><<<(BATCH * N_DOWN) / 128, 1024, SM_TOTAL>>>(x_down, nullptr, bimg0, b_lin, nullptr);
    gemm_mma<2><<<(BATCH * N_UP) / 128, 1024, SM_TOTAL>>>(x_up, up_idx, bimg1, b_fus, out);
}